// round 1
// baseline (speedup 1.0000x reference)
#include <cuda_runtime.h>
#include <math.h>

// Problem constants (fixed by the dataset)
#define RR 8
#define NN 128
#define DD 512
#define HH 256
#define KTOP 64
#define NPAIR (NN*NN)          // 16384

// Device scratch (no allocations allowed)
__device__ float g_pf[KTOP * DD];     // gathered mean pair features [64][512]
__device__ int   g_topk[KTOP];
__device__ float g_probs[NPAIR];

// ---------------------------------------------------------------------------
// Fused MLP scorer:  logit(row) = sum_h relu( x(row)·W1[:,h] + b1[h] ) * w2[h]
// PHASE 0: rows = 4 (i,j) pairs x 8 replicas; x = obj_i ⊙ obj_j + geo; output
//          is the r-mean logit per pair, written to outv[pair].
// PHASE 1: rows = 32 (s,t) p2p pairs; x = pf_s ⊙ pf_t; output per row.
// Block: 256 threads.  Register blocking: 8 rows x 4 h per thread.
// ---------------------------------------------------------------------------
template <int PHASE>
__global__ __launch_bounds__(256)
void mlp_score_kernel(const float* __restrict__ obj,
                      const float* __restrict__ geo,
                      const float* __restrict__ w1,
                      const float* __restrict__ b1,
                      const float* __restrict__ w2,
                      const float* __restrict__ b2,
                      float* __restrict__ outv)
{
    __shared__ float x_s[32][16];
    __shared__ float w_s[16][HH];
    __shared__ float red[32][65];
    __shared__ float rowlogit[32];

    const int t  = threadIdx.x;
    const int rg = t >> 6;      // row group 0..3 (8 rows each)
    const int hg = t & 63;      // h group 0..63 (4 h each)

    float acc[8][4];
#pragma unroll
    for (int a = 0; a < 8; a++)
#pragma unroll
        for (int b = 0; b < 4; b++) acc[a][b] = 0.f;

#pragma unroll 1
    for (int k0 = 0; k0 < DD; k0 += 16) {
        // ---- load W chunk [16][256] ----
#pragma unroll
        for (int it = 0; it < 4; it++) {
            int idx = t + 256 * it;        // float4 id 0..1023
            int kk  = idx >> 6;            // 0..15
            int h4  = idx & 63;            // 0..63
            *(float4*)&w_s[kk][h4 * 4] =
                *(const float4*)&w1[(size_t)(k0 + kk) * HH + h4 * 4];
        }
        // ---- load/build X chunk [32][16] ----
        if (t < 128) {
            int row = t >> 2;              // 0..31
            int q   = t & 3;               // float4 quarter of the 16-wide chunk
            float4 xv;
            if (PHASE == 0) {
                int pb = blockIdx.x * 4;
                int pl = row >> 3, r = row & 7;
                int p = pb + pl;
                int i = p >> 7, j = p & 127;
                const float4 g4 = *(const float4*)&geo[
                    ((((size_t)r * NN + i) * NN + j) * DD) + k0 + q * 4];
                const float4 oi = *(const float4*)&obj[
                    ((size_t)(r * NN + i)) * DD + k0 + q * 4];
                const float4 oj = *(const float4*)&obj[
                    ((size_t)(r * NN + j)) * DD + k0 + q * 4];
                xv.x = fmaf(oi.x, oj.x, g4.x);
                xv.y = fmaf(oi.y, oj.y, g4.y);
                xv.z = fmaf(oi.z, oj.z, g4.z);
                xv.w = fmaf(oi.w, oj.w, g4.w);
            } else {
                int rowg = blockIdx.x * 32 + row;    // 0..4095
                int s = rowg >> 6, u = rowg & 63;
                const float4 a4 = *(const float4*)&g_pf[s * DD + k0 + q * 4];
                const float4 c4 = *(const float4*)&g_pf[u * DD + k0 + q * 4];
                xv.x = a4.x * c4.x; xv.y = a4.y * c4.y;
                xv.z = a4.z * c4.z; xv.w = a4.w * c4.w;
            }
            *(float4*)&x_s[row][q * 4] = xv;
        }
        __syncthreads();

        // ---- compute: 16 k-steps, 8 rows x 4 h per thread ----
#pragma unroll
        for (int k = 0; k < 16; k++) {
            float4 w4 = *(float4*)&w_s[k][hg << 2];
#pragma unroll
            for (int r2 = 0; r2 < 8; r2++) {
                float xv = x_s[(rg << 3) + r2][k];
                acc[r2][0] = fmaf(xv, w4.x, acc[r2][0]);
                acc[r2][1] = fmaf(xv, w4.y, acc[r2][1]);
                acc[r2][2] = fmaf(xv, w4.z, acc[r2][2]);
                acc[r2][3] = fmaf(xv, w4.w, acc[r2][3]);
            }
        }
        __syncthreads();
    }

    // ---- epilogue: bias, relu, dot w2, reduce over h ----
    const float4 bb = *(const float4*)&b1[hg * 4];
    const float4 ww = *(const float4*)&w2[hg * 4];
#pragma unroll
    for (int r2 = 0; r2 < 8; r2++) {
        float z0 = acc[r2][0] + bb.x;
        float z1 = acc[r2][1] + bb.y;
        float z2 = acc[r2][2] + bb.z;
        float z3 = acc[r2][3] + bb.w;
        float p = fmaxf(z0, 0.f) * ww.x + fmaxf(z1, 0.f) * ww.y
                + fmaxf(z2, 0.f) * ww.z + fmaxf(z3, 0.f) * ww.w;
        red[(rg << 3) + r2][hg] = p;
    }
    __syncthreads();
    if (t < 32) {
        float s = 0.f;
#pragma unroll 8
        for (int c = 0; c < 64; c++) s += red[t][c];
        rowlogit[t] = s;
    }
    __syncthreads();

    if (PHASE == 0) {
        if (t < 4) {
            float s = 0.f;
#pragma unroll
            for (int r = 0; r < 8; r++) s += rowlogit[t * 8 + r];
            outv[blockIdx.x * 4 + t] = s * (1.f / RR) + b2[0];
        }
    } else {
        if (t < 32) outv[blockIdx.x * 32 + t] = rowlogit[t] + b2[0];
    }
}

// ---------------------------------------------------------------------------
// top-64 of sigmoid(logit)*mask, JAX tie semantics (value desc, index asc)
// ---------------------------------------------------------------------------
__global__ void topk_kernel(const float* __restrict__ logits,
                            const float* __restrict__ mask,
                            float* __restrict__ out_inds)
{
    const int t = threadIdx.x;
    for (int p = t; p < NPAIR; p += 256) {
        float l = logits[p];
        float prob = 1.f / (1.f + expf(-l));
        g_probs[p] = prob * mask[p];
    }
    __syncthreads();

    __shared__ float wv[8];
    __shared__ int   wi[8];
    for (int sel = 0; sel < KTOP; sel++) {
        float bv = -1.f;
        int   bi = 1 << 30;
        for (int p = t; p < NPAIR; p += 256) {
            float v = g_probs[p];
            if (v > bv || (v == bv && p < bi)) { bv = v; bi = p; }
        }
#pragma unroll
        for (int o = 16; o > 0; o >>= 1) {
            float ov = __shfl_down_sync(0xffffffffu, bv, o);
            int   oi = __shfl_down_sync(0xffffffffu, bi, o);
            if (ov > bv || (ov == bv && oi < bi)) { bv = ov; bi = oi; }
        }
        if ((t & 31) == 0) { wv[t >> 5] = bv; wi[t >> 5] = bi; }
        __syncthreads();
        if (t == 0) {
            for (int w = 1; w < 8; w++) {
                if (wv[w] > bv || (wv[w] == bv && wi[w] < bi)) { bv = wv[w]; bi = wi[w]; }
            }
            g_topk[sel] = bi;
            out_inds[sel] = (float)bi;
            g_probs[bi] = -2.f;
        }
        __syncthreads();
    }
}

// ---------------------------------------------------------------------------
// gather mean pair features for the 64 selected (i,j) pairs
// pf[t][d] = (1/R) sum_r ( obj[r,i,d]*obj[r,j,d] + geo[r,i,j,d] )
// ---------------------------------------------------------------------------
__global__ void gather_pf_kernel(const float* __restrict__ obj,
                                 const float* __restrict__ geo)
{
    const int b = blockIdx.x;      // 0..63
    const int ind = g_topk[b];
    const int i = ind >> 7, j = ind & 127;
    const int d = threadIdx.x * 4; // 128 threads x float4
    float4 a = make_float4(0.f, 0.f, 0.f, 0.f);
#pragma unroll
    for (int r = 0; r < RR; r++) {
        const float4 oi = *(const float4*)&obj[((size_t)(r * NN + i)) * DD + d];
        const float4 oj = *(const float4*)&obj[((size_t)(r * NN + j)) * DD + d];
        const float4 g4 = *(const float4*)&geo[((((size_t)r * NN + i) * NN + j) * DD) + d];
        a.x += fmaf(oi.x, oj.x, g4.x);
        a.y += fmaf(oi.y, oj.y, g4.y);
        a.z += fmaf(oi.z, oj.z, g4.z);
        a.w += fmaf(oi.w, oj.w, g4.w);
    }
    a.x *= (1.f / RR); a.y *= (1.f / RR); a.z *= (1.f / RR); a.w *= (1.f / RR);
    *(float4*)&g_pf[b * DD + d] = a;
}

// ---------------------------------------------------------------------------
extern "C" void kernel_launch(void* const* d_in, const int* in_sizes, int n_in,
                              void* d_out, int out_size)
{
    const float* obj  = (const float*)d_in[0];
    const float* geo  = (const float*)d_in[1];
    const float* mask = (const float*)d_in[2];
    const float* w1a  = (const float*)d_in[3];
    const float* b1a  = (const float*)d_in[4];
    const float* w2a  = (const float*)d_in[5];
    const float* b2a  = (const float*)d_in[6];
    const float* w1b  = (const float*)d_in[7];
    const float* b1b  = (const float*)d_in[8];
    const float* w2b  = (const float*)d_in[9];
    const float* b2b  = (const float*)d_in[10];
    float* out = (float*)d_out;

    // Phase 1: o2o logits (r-averaged) -> out[0:16384]
    mlp_score_kernel<0><<<NPAIR / 4, 256>>>(obj, geo, w1a, b1a, w2a, b2a, out);
    // Phase 2: top-64 -> g_topk, indices as float -> out[20480:20544]
    topk_kernel<<<1, 256>>>(out, mask, out + NPAIR + KTOP * KTOP);
    // Phase 3: gather mean pair features for selected pairs
    gather_pf_kernel<<<KTOP, 128>>>(obj, geo);
    // Phase 4: p2p logits -> out[16384:20480]
    mlp_score_kernel<1><<<KTOP * KTOP / 32, 256>>>(obj, geo, w1b, b1b, w2b, b2b,
                                                   out + NPAIR);
}

// round 4
// speedup vs baseline: 1.4601x; 1.4601x over previous
#include <cuda_runtime.h>
#include <cuda_bf16.h>
#include <cstdint>
#include <math.h>

// ---------------------------------------------------------------- constants
#define RR 8
#define NN 128
#define DD 512
#define HH 256
#define KTOP 64
#define NPAIR (NN*NN)          // 16384
#define KC 64                  // K per chunk (64 bf16 = 128B rows, SW128 atom)
#define NCH 8                  // 512 / 64
#define STG 98304              // bytes per smem stage (A_hi+A_lo+B_hi+B_lo)
#define OFF_AHI 0
#define OFF_ALO 16384
#define OFF_BHI 32768
#define OFF_BLO 65536
#define SWZ(o) ((o) ^ (((o) >> 3) & 0x70))

// ---------------------------------------------------------------- scratch
__device__ float g_pf[KTOP * DD];                     // gathered mean pair feats
__device__ int   g_topk[KTOP];
__device__ __align__(16) __nv_bfloat16 g_whi[2][NCH * 16384]; // pre-split W (hi)
__device__ __align__(16) __nv_bfloat16 g_wlo[2][NCH * 16384]; // pre-split W (lo)

// ---------------------------------------------------------------- helpers
static __device__ __forceinline__ uint32_t smem_u32(const void* p) {
    uint32_t a;
    asm("{ .reg .u64 t; cvta.to.shared.u64 t, %1; cvt.u32.u64 %0, t; }"
        : "=r"(a) : "l"(p));
    return a;
}
static __device__ __forceinline__ void ldsm4(uint32_t* r, uint32_t addr) {
    asm volatile("ldmatrix.sync.aligned.m8n8.x4.shared.b16 {%0,%1,%2,%3}, [%4];"
                 : "=r"(r[0]), "=r"(r[1]), "=r"(r[2]), "=r"(r[3]) : "r"(addr));
}
static __device__ __forceinline__ void mma16816(float* d, const uint32_t* a,
                                                uint32_t b0, uint32_t b1) {
    asm volatile(
        "mma.sync.aligned.m16n8k16.row.col.f32.bf16.bf16.f32 "
        "{%0,%1,%2,%3}, {%4,%5,%6,%7}, {%8,%9}, {%0,%1,%2,%3};"
        : "+f"(d[0]), "+f"(d[1]), "+f"(d[2]), "+f"(d[3])
        : "r"(a[0]), "r"(a[1]), "r"(a[2]), "r"(a[3]), "r"(b0), "r"(b1));
}
#define CP_ASYNC16(dst, src) \
    asm volatile("cp.async.cg.shared.global [%0], [%1], 16;" \
                 :: "r"(dst), "l"(src) : "memory")
#define CP_COMMIT() asm volatile("cp.async.commit_group;" ::: "memory")
#define CP_WAIT0()  asm volatile("cp.async.wait_group 0;" ::: "memory")

// split one float pair into packed bf16 hi (returned) + residuals
static __device__ __forceinline__ uint32_t pkhi(float a, float b,
                                                float& ra, float& rb) {
    __nv_bfloat16 ha = __float2bfloat16(a), hb = __float2bfloat16(b);
    ra = a - __bfloat162float(ha);
    rb = b - __bfloat162float(hb);
    __nv_bfloat162 h2 = __halves2bfloat162(ha, hb);
    return *reinterpret_cast<uint32_t*>(&h2);
}
static __device__ __forceinline__ uint32_t pklo(float a, float b) {
    __nv_bfloat162 h2 = __floats2bfloat162_rn(a, b);
    return *reinterpret_cast<uint32_t*>(&h2);
}

// ---------------------------------------------------------------- W prep
// Split W1 (fp32 [512,256]) into bf16 hi/lo, transposed to [n][k] per K-chunk,
// in the exact swizzled byte layout the GEMM's smem B tile uses.
__global__ void prep_w_kernel(const float* __restrict__ w1a,
                              const float* __restrict__ w1b) {
    int idx = blockIdx.x * 256 + threadIdx.x;      // 0..262143
    int arr = idx >> 17;
    int rem = idx & 131071;
    int c  = rem >> 14;
    int n  = (rem >> 6) & 255;
    int kk = rem & 63;
    const float* w = arr ? w1b : w1a;
    float f = w[(size_t)(c * 64 + kk) * HH + n];
    __nv_bfloat16 hi = __float2bfloat16(f);
    __nv_bfloat16 lo = __float2bfloat16(f - __bfloat162float(hi));
    uint32_t off = (uint32_t)c * 32768u + SWZ((uint32_t)(n * 128 + kk * 2));
    *(__nv_bfloat16*)((char*)g_whi[arr] + off) = hi;
    *(__nv_bfloat16*)((char*)g_wlo[arr] + off) = lo;
}

// ---------------------------------------------------------------- fused GEMM
// PHASE 0: 1024 blocks, tile = 16 pairs x 8 replicas (M=128); X = oi*oj + geo.
//          Epilogue r-mean -> out[pair].
// PHASE 1: 32 blocks, tile = 128 p2p pairs; X = pf_s * pf_u. Per-row output.
// 8 warps: warp grid 2(M) x 4(N), warp tile 64x64, mma.sync m16n8k16 bf16.
// acc = hi*hi + hi*lo + lo*hi  (bf16x3 split, fp32 accumulate).
template <int PHASE>
__global__ __launch_bounds__(256, 1)
void gemm_mlp_kernel(const float* __restrict__ obj, const float* __restrict__ geo,
                     const float* __restrict__ b1, const float* __restrict__ w2,
                     const float* __restrict__ b2, float* __restrict__ outv) {
    extern __shared__ char smraw[];
    char* sm = (char*)(((uintptr_t)smraw + 1023) & ~(uintptr_t)1023);
    __shared__ float s_b1[HH], s_w2[HH];
    __shared__ float red[128][5];
    __shared__ float rowlogit[128];

    const int t = threadIdx.x;
    const int wid = t >> 5, lane = t & 31;
    const int wm = wid >> 2;           // 0..1  (M warp)
    const int wn = wid & 3;            // 0..3  (N warp)
    const uint32_t smb = smem_u32(sm);

    s_b1[t] = b1[t];
    s_w2[t] = w2[t];

    // per-thread X source: row = t>>1 (0..127), k-half qb = (t&1)*32
    const int row = t >> 1;
    const int qb  = (t & 1) * 32;
    const float *xip, *xjp, *xgp = nullptr;
    if (PHASE == 0) {
        int pl = row >> 3, r = row & 7;
        int p = blockIdx.x * 16 + pl;
        int i = p >> 7, j = p & 127;
        xgp = geo + (size_t)((r * NN + i) * NN + j) * DD + qb;
        xip = obj + (size_t)(r * NN + i) * DD + qb;
        xjp = obj + (size_t)(r * NN + j) * DD + qb;
    } else {
        int g = blockIdx.x * 128 + row;
        xip = g_pf + (g >> 6) * DD + qb;
        xjp = g_pf + (g & 63) * DD + qb;
    }
    const char* wsrcH = (const char*)g_whi[PHASE];
    const char* wsrcL = (const char*)g_wlo[PHASE];
    const uint32_t arow = (uint32_t)(row * 128 + qb * 2);  // A-tile byte base

    float acc[4][8][4];
#pragma unroll
    for (int a = 0; a < 4; a++)
#pragma unroll
        for (int b = 0; b < 8; b++)
#pragma unroll
            for (int cq = 0; cq < 4; cq++) acc[a][b][cq] = 0.f;

    // build X chunk c into packed hi/lo regs
    uint4 xh[4], xl[4];
    auto buildX = [&](int c) {
        float4 x[8];
#pragma unroll
        for (int m = 0; m < 8; m++) {
            float4 a = ((const float4*)(xip + c * KC))[m];
            float4 b = ((const float4*)(xjp + c * KC))[m];
            if (PHASE == 0) {
                float4 g4 = ((const float4*)(xgp + c * KC))[m];
                x[m].x = fmaf(a.x, b.x, g4.x);
                x[m].y = fmaf(a.y, b.y, g4.y);
                x[m].z = fmaf(a.z, b.z, g4.z);
                x[m].w = fmaf(a.w, b.w, g4.w);
            } else {
                x[m].x = a.x * b.x; x[m].y = a.y * b.y;
                x[m].z = a.z * b.z; x[m].w = a.w * b.w;
            }
        }
#pragma unroll
        for (int m = 0; m < 4; m++) {
            float r0, r1, r2, r3, r4, r5, r6, r7;
            xh[m].x = pkhi(x[2*m].x,   x[2*m].y,   r0, r1);
            xh[m].y = pkhi(x[2*m].z,   x[2*m].w,   r2, r3);
            xh[m].z = pkhi(x[2*m+1].x, x[2*m+1].y, r4, r5);
            xh[m].w = pkhi(x[2*m+1].z, x[2*m+1].w, r6, r7);
            xl[m].x = pklo(r0, r1);
            xl[m].y = pklo(r2, r3);
            xl[m].z = pklo(r4, r5);
            xl[m].w = pklo(r6, r7);
        }
    };

    buildX(0);
    // lane-level ldmatrix address components
    const uint32_t aRow = (uint32_t)(wm * 64 + (lane & 15));
    const uint32_t nRow = (uint32_t)(wn * 64 + (lane & 15));
    const uint32_t kbL  = (uint32_t)((lane >> 4) * 16);

#pragma unroll 1
    for (int c = 0; c < NCH; c++) {
        const int st = c & 1;
        char* sb = sm + st * STG;
        const uint32_t sbb = smb + st * STG;
        __syncthreads();                 // stage st free (ldmatrix of c-2 done)
        // ---- STS X ----
#pragma unroll
        for (int m = 0; m < 4; m++) {
            *(uint4*)(sb + OFF_AHI + SWZ(arow + m * 16)) = xh[m];
            *(uint4*)(sb + OFF_ALO + SWZ(arow + m * 16)) = xl[m];
        }
        // ---- cp.async W chunk (gmem, L2-hot) -> smem B tiles ----
        {
            uint32_t dH = sbb + OFF_BHI + t * 128;
            uint32_t dL = sbb + OFF_BLO + t * 128;
            const char* sH = wsrcH + c * 32768 + t * 128;
            const char* sL = wsrcL + c * 32768 + t * 128;
#pragma unroll
            for (int m = 0; m < 8; m++) {
                CP_ASYNC16(dH + m * 16, sH + m * 16);
                CP_ASYNC16(dL + m * 16, sL + m * 16);
            }
            CP_COMMIT();
        }
        // ---- overlap: build next chunk's X while cp.async lands ----
        if (c + 1 < NCH) buildX(c + 1);
        CP_WAIT0();
        __syncthreads();
        // ---- MMA over stage st ----
        const uint32_t sAhi = sbb + OFF_AHI, sAlo = sbb + OFF_ALO;
        const uint32_t sBhi = sbb + OFF_BHI, sBlo = sbb + OFF_BLO;
#pragma unroll
        for (int ks = 0; ks < 4; ks++) {
            const uint32_t kbase = ks * 32 + kbL;
            uint32_t ah[4][4], al[4][4];
#pragma unroll
            for (int mt = 0; mt < 4; mt++) {
                uint32_t off = SWZ((aRow + mt * 16) * 128 + kbase);
                ldsm4(ah[mt], sAhi + off);
                ldsm4(al[mt], sAlo + off);
            }
#pragma unroll
            for (int nh = 0; nh < 2; nh++) {
                uint32_t bh[2][4], bl[2][4];
#pragma unroll
                for (int p = 0; p < 2; p++) {
                    uint32_t off = SWZ((nRow + nh * 32 + p * 16) * 128 + kbase);
                    ldsm4(bh[p], sBhi + off);
                    ldsm4(bl[p], sBlo + off);
                }
#pragma unroll
                for (int mt = 0; mt < 4; mt++)
#pragma unroll
                    for (int p = 0; p < 2; p++)
#pragma unroll
                        for (int e = 0; e < 2; e++) {
                            float* d = acc[mt][nh * 4 + p * 2 + e];
                            mma16816(d, ah[mt], bh[p][e], bh[p][e + 2]);
                            mma16816(d, ah[mt], bl[p][e], bl[p][e + 2]);
                            mma16816(d, al[mt], bh[p][e], bh[p][e + 2]);
                        }
            }
        }
    }

    // ---- epilogue: bias, relu, dot w2 ----
    // D frag: rows wm*64+mt*16+(lane>>2) and +8; cols wn*64+nt*8+(lane&3)*2+{0,1}
#pragma unroll
    for (int mt = 0; mt < 4; mt++) {
        float ps0 = 0.f, ps1 = 0.f;
#pragma unroll
        for (int nt = 0; nt < 8; nt++) {
            int h = wn * 64 + nt * 8 + (lane & 3) * 2;
            float b0 = s_b1[h],  w0 = s_w2[h];
            float b1v = s_b1[h + 1], w1v = s_w2[h + 1];
            ps0 = fmaf(fmaxf(acc[mt][nt][0] + b0, 0.f),  w0,  ps0);
            ps0 = fmaf(fmaxf(acc[mt][nt][1] + b1v, 0.f), w1v, ps0);
            ps1 = fmaf(fmaxf(acc[mt][nt][2] + b0, 0.f),  w0,  ps1);
            ps1 = fmaf(fmaxf(acc[mt][nt][3] + b1v, 0.f), w1v, ps1);
        }
        ps0 += __shfl_xor_sync(0xffffffffu, ps0, 1);
        ps0 += __shfl_xor_sync(0xffffffffu, ps0, 2);
        ps1 += __shfl_xor_sync(0xffffffffu, ps1, 1);
        ps1 += __shfl_xor_sync(0xffffffffu, ps1, 2);
        if ((lane & 3) == 0) {
            int r0 = wm * 64 + mt * 16 + (lane >> 2);
            red[r0][wn] = ps0;
            red[r0 + 8][wn] = ps1;
        }
    }
    __syncthreads();
    if (t < 128) rowlogit[t] = red[t][0] + red[t][1] + red[t][2] + red[t][3];
    __syncthreads();
    if (PHASE == 0) {
        if (t < 16) {
            float s = 0.f;
#pragma unroll
            for (int r = 0; r < 8; r++) s += rowlogit[t * 8 + r];
            outv[blockIdx.x * 16 + t] = s * 0.125f + b2[0];
        }
    } else {
        if (t < 128) outv[blockIdx.x * 128 + t] = rowlogit[t] + b2[0];
    }
}

// ---------------------------------------------------------------- top-64
// Register-resident iterative selection: tie semantics = value desc, index asc.
// Ordering by logit == ordering by sigmoid(logit); masked entries -> -inf.
__global__ __launch_bounds__(1024) void topk_kernel(const float* __restrict__ logits,
                                                    const float* __restrict__ mask,
                                                    float* __restrict__ out_inds) {
    const int t = threadIdx.x;
    const int wid = t >> 5, lane = t & 31;
    float v[16];
#pragma unroll
    for (int u = 0; u < 16; u++) {
        int p = u * 1024 + t;
        v[u] = (mask[p] != 0.f) ? logits[p] : -3.4e38f;
    }
    float lmax = -3.4e38f; int ls = 0;
#pragma unroll
    for (int u = 0; u < 16; u++) if (v[u] > lmax) { lmax = v[u]; ls = u; }

    __shared__ float wv[32];
    __shared__ int wi2[32];
    __shared__ int s_best;
    for (int sel = 0; sel < KTOP; sel++) {
        float bv = lmax;
        int bi = ls * 1024 + t;
#pragma unroll
        for (int o = 16; o > 0; o >>= 1) {
            float ov = __shfl_down_sync(0xffffffffu, bv, o);
            int oi = __shfl_down_sync(0xffffffffu, bi, o);
            if (ov > bv || (ov == bv && oi < bi)) { bv = ov; bi = oi; }
        }
        if (lane == 0) { wv[wid] = bv; wi2[wid] = bi; }
        __syncthreads();
        if (wid == 0) {
            bv = wv[lane]; bi = wi2[lane];
#pragma unroll
            for (int o = 16; o > 0; o >>= 1) {
                float ov = __shfl_down_sync(0xffffffffu, bv, o);
                int oi = __shfl_down_sync(0xffffffffu, bi, o);
                if (ov > bv || (ov == bv && oi < bi)) { bv = ov; bi = oi; }
            }
            if (lane == 0) { g_topk[sel] = bi; out_inds[sel] = (float)bi; s_best = bi; }
        }
        __syncthreads();
        int w = s_best;
        if ((w & 1023) == t) {
            v[w >> 10] = -3.4e38f;
            lmax = -3.4e38f; ls = 0;
#pragma unroll
            for (int u = 0; u < 16; u++) if (v[u] > lmax) { lmax = v[u]; ls = u; }
        }
    }
}

// ---------------------------------------------------------------- gather
__global__ void gather_pf_kernel(const float* __restrict__ obj,
                                 const float* __restrict__ geo) {
    const int b = blockIdx.x;
    const int ind = g_topk[b];
    const int i = ind >> 7, j = ind & 127;
    const int d = threadIdx.x * 4;
    float4 a = make_float4(0.f, 0.f, 0.f, 0.f);
#pragma unroll
    for (int r = 0; r < RR; r++) {
        const float4 oi = *(const float4*)&obj[(size_t)(r * NN + i) * DD + d];
        const float4 oj = *(const float4*)&obj[(size_t)(r * NN + j) * DD + d];
        const float4 g4 = *(const float4*)&geo[(size_t)((r * NN + i) * NN + j) * DD + d];
        a.x += fmaf(oi.x, oj.x, g4.x);
        a.y += fmaf(oi.y, oj.y, g4.y);
        a.z += fmaf(oi.z, oj.z, g4.z);
        a.w += fmaf(oi.w, oj.w, g4.w);
    }
    a.x *= (1.f / RR); a.y *= (1.f / RR); a.z *= (1.f / RR); a.w *= (1.f / RR);
    *(float4*)&g_pf[b * DD + d] = a;
}

// ---------------------------------------------------------------- launch
extern "C" void kernel_launch(void* const* d_in, const int* in_sizes, int n_in,
                              void* d_out, int out_size) {
    const float* obj  = (const float*)d_in[0];
    const float* geo  = (const float*)d_in[1];
    const float* mask = (const float*)d_in[2];
    const float* w1a  = (const float*)d_in[3];
    const float* b1a  = (const float*)d_in[4];
    const float* w2a  = (const float*)d_in[5];
    const float* b2a  = (const float*)d_in[6];
    const float* w1b  = (const float*)d_in[7];
    const float* b1b  = (const float*)d_in[8];
    const float* w2b  = (const float*)d_in[9];
    const float* b2b  = (const float*)d_in[10];
    float* out = (float*)d_out;

    const int dyn = 2 * STG + 1024;  // +1024 for manual alignment
    cudaFuncSetAttribute(gemm_mlp_kernel<0>,
                         cudaFuncAttributeMaxDynamicSharedMemorySize, dyn);
    cudaFuncSetAttribute(gemm_mlp_kernel<1>,
                         cudaFuncAttributeMaxDynamicSharedMemorySize, dyn);

    prep_w_kernel<<<1024, 256>>>(w1a, w1b);
    gemm_mlp_kernel<0><<<NPAIR / 16, 256, dyn>>>(obj, geo, b1a, w2a, b2a, out);
    topk_kernel<<<1, 1024>>>(out, mask, out + NPAIR + KTOP * KTOP);
    gather_pf_kernel<<<KTOP, 128>>>(obj, geo);
    gemm_mlp_kernel<1><<<KTOP * KTOP / 128, 256, dyn>>>(obj, geo, b1b, w2b, b2b,
                                                        out + NPAIR);
}

// round 6
// speedup vs baseline: 2.3363x; 1.6001x over previous
#include <cuda_runtime.h>
#include <cuda_bf16.h>
#include <cstdint>
#include <math.h>

// ---------------------------------------------------------------- constants
#define RR 8
#define NN 128
#define DD 512
#define HH 256
#define KTOP 64
#define NPAIR (NN*NN)          // 16384
#define KC 64                  // K per chunk (64 bf16 = 128B rows, SW128 atom)
#define NCH 8                  // 512 / 64
#define STG 98304              // bytes per smem stage (A_hi+A_lo+B_hi+B_lo)
#define OFF_AHI 0
#define OFF_ALO 16384
#define OFF_BHI 32768
#define OFF_BLO 65536
#define SWZ(o) ((o) ^ (((o) >> 3) & 0x70))

// ---------------------------------------------------------------- scratch
__device__ float g_pf[KTOP * DD];                     // gathered mean pair feats
__device__ int   g_topk[KTOP];
__device__ __align__(16) __nv_bfloat16 g_whi[2][NCH * 16384]; // pre-split W (hi)
__device__ __align__(16) __nv_bfloat16 g_wlo[2][NCH * 16384]; // pre-split W (lo)

// ---------------------------------------------------------------- helpers
static __device__ __forceinline__ uint32_t smem_u32(const void* p) {
    uint32_t a;
    asm("{ .reg .u64 t; cvta.to.shared.u64 t, %1; cvt.u32.u64 %0, t; }"
        : "=r"(a) : "l"(p));
    return a;
}
static __device__ __forceinline__ void ldsm4(uint32_t* r, uint32_t addr) {
    asm volatile("ldmatrix.sync.aligned.m8n8.x4.shared.b16 {%0,%1,%2,%3}, [%4];"
                 : "=r"(r[0]), "=r"(r[1]), "=r"(r[2]), "=r"(r[3]) : "r"(addr));
}
static __device__ __forceinline__ void mma16816(float* d, const uint32_t* a,
                                                uint32_t b0, uint32_t b1) {
    asm volatile(
        "mma.sync.aligned.m16n8k16.row.col.f32.bf16.bf16.f32 "
        "{%0,%1,%2,%3}, {%4,%5,%6,%7}, {%8,%9}, {%0,%1,%2,%3};"
        : "+f"(d[0]), "+f"(d[1]), "+f"(d[2]), "+f"(d[3])
        : "r"(a[0]), "r"(a[1]), "r"(a[2]), "r"(a[3]), "r"(b0), "r"(b1));
}
#define CP_ASYNC16(dst, src) \
    asm volatile("cp.async.cg.shared.global [%0], [%1], 16;" \
                 :: "r"(dst), "l"(src) : "memory")
#define CP_COMMIT() asm volatile("cp.async.commit_group;" ::: "memory")
#define CP_WAIT0()  asm volatile("cp.async.wait_group 0;" ::: "memory")

// split one float pair into packed bf16 hi (returned) + residuals
static __device__ __forceinline__ uint32_t pkhi(float a, float b,
                                                float& ra, float& rb) {
    __nv_bfloat16 ha = __float2bfloat16(a), hb = __float2bfloat16(b);
    ra = a - __bfloat162float(ha);
    rb = b - __bfloat162float(hb);
    __nv_bfloat162 h2 = __halves2bfloat162(ha, hb);
    return *reinterpret_cast<uint32_t*>(&h2);
}
static __device__ __forceinline__ uint32_t pklo(float a, float b) {
    __nv_bfloat162 h2 = __floats2bfloat162_rn(a, b);
    return *reinterpret_cast<uint32_t*>(&h2);
}

// ---------------------------------------------------------------- W prep
// Split W1 (fp32 [512,256]) into bf16 hi/lo, transposed to [n][k] per K-chunk,
// in the exact swizzled byte layout the GEMM's smem B tile uses.
__global__ void prep_w_kernel(const float* __restrict__ w1a,
                              const float* __restrict__ w1b) {
    int idx = blockIdx.x * 256 + threadIdx.x;      // 0..262143
    int arr = idx >> 17;
    int rem = idx & 131071;
    int c  = rem >> 14;
    int n  = (rem >> 6) & 255;
    int kk = rem & 63;
    const float* w = arr ? w1b : w1a;
    float f = w[(size_t)(c * 64 + kk) * HH + n];
    __nv_bfloat16 hi = __float2bfloat16(f);
    __nv_bfloat16 lo = __float2bfloat16(f - __bfloat162float(hi));
    uint32_t off = (uint32_t)c * 32768u + SWZ((uint32_t)(n * 128 + kk * 2));
    *(__nv_bfloat16*)((char*)g_whi[arr] + off) = hi;
    *(__nv_bfloat16*)((char*)g_wlo[arr] + off) = lo;
}

// ---------------------------------------------------------------- fused GEMM
// PHASE 0: 1024 blocks, tile = 16 pairs x 8 replicas (M=128); X = oi*oj + geo.
//          Epilogue r-mean -> out[pair].
// PHASE 1: 32 blocks, tile = 128 p2p pairs; X = pf_s * pf_u. Per-row output.
// 8 warps: warp grid 2(M) x 4(N), warp tile 64x64, mma.sync m16n8k16 bf16.
// acc = hi*hi + hi*lo + lo*hi  (bf16x3 split, fp32 accumulate).
// X-build / W-copy are warp-coalesced: 4 x 128B lines per LDG/cp.async instr.
template <int PHASE>
__global__ __launch_bounds__(256, 1)
void gemm_mlp_kernel(const float* __restrict__ obj, const float* __restrict__ geo,
                     const float* __restrict__ b1, const float* __restrict__ w2,
                     const float* __restrict__ b2, float* __restrict__ outv) {
    extern __shared__ char smraw[];
    char* sm = (char*)(((uintptr_t)smraw + 1023) & ~(uintptr_t)1023);
    __shared__ float s_b1[HH], s_w2[HH];
    __shared__ float red[128][5];
    __shared__ float rowlogit[128];

    const int t = threadIdx.x;
    const int wid = t >> 5, lane = t & 31;
    const int wm = wid >> 2;           // 0..1  (M warp)
    const int wn = wid & 3;            // 0..3  (N warp)
    const uint32_t smb = smem_u32(sm);

    s_b1[t] = b1[t];
    s_w2[t] = w2[t];

    const char* wsrcH = (const char*)g_whi[PHASE];
    const char* wsrcL = (const char*)g_wlo[PHASE];

    // X-build ownership: warp w -> rows 16w..16w+15; per iter m the warp loads
    // rows 16w+2m (lanes 0-15) and 16w+2m+1 (lanes 16-31); lane&15 = float4 idx.
    const int rbase = (wid << 4) + (lane >> 4);   // + 2m per iter
    const int f4    = lane & 15;

    float acc[4][8][4];
#pragma unroll
    for (int a = 0; a < 4; a++)
#pragma unroll
        for (int b = 0; b < 8; b++)
#pragma unroll
            for (int cq = 0; cq < 4; cq++) acc[a][b][cq] = 0.f;

    uint2 xh2[8], xl2[8];
    auto buildX = [&](int c) {
#pragma unroll
        for (int m = 0; m < 8; m++) {
            const int row = rbase + 2 * m;
            float4 x;
            if (PHASE == 0) {
                int pl = row >> 3, r = row & 7;
                int p = blockIdx.x * 16 + pl;
                int i = p >> 7, j = p & 127;
                const float4 a = *(const float4*)(obj + (size_t)(r * NN + i) * DD
                                                  + c * KC + f4 * 4);
                const float4 b = *(const float4*)(obj + (size_t)(r * NN + j) * DD
                                                  + c * KC + f4 * 4);
                const float4 g4 = *(const float4*)(geo
                    + (size_t)((r * NN + i) * NN + j) * DD + c * KC + f4 * 4);
                x.x = fmaf(a.x, b.x, g4.x);
                x.y = fmaf(a.y, b.y, g4.y);
                x.z = fmaf(a.z, b.z, g4.z);
                x.w = fmaf(a.w, b.w, g4.w);
            } else {
                int g = blockIdx.x * 128 + row;
                const float4 a = *(const float4*)(g_pf + (g >> 6) * DD
                                                  + c * KC + f4 * 4);
                const float4 b = *(const float4*)(g_pf + (g & 63) * DD
                                                  + c * KC + f4 * 4);
                x.x = a.x * b.x; x.y = a.y * b.y;
                x.z = a.z * b.z; x.w = a.w * b.w;
            }
            float r0, r1, r2, r3;
            xh2[m].x = pkhi(x.x, x.y, r0, r1);
            xh2[m].y = pkhi(x.z, x.w, r2, r3);
            xl2[m].x = pklo(r0, r1);
            xl2[m].y = pklo(r2, r3);
        }
    };

    buildX(0);
    // lane-level ldmatrix address components
    const uint32_t aRow = (uint32_t)(wm * 64 + (lane & 15));
    const uint32_t nRow = (uint32_t)(wn * 64 + (lane & 15));
    const uint32_t kbL  = (uint32_t)((lane >> 4) * 16);

#pragma unroll 1
    for (int c = 0; c < NCH; c++) {
        const int st = c & 1;
        char* sb = sm + st * STG;
        const uint32_t sbb = smb + st * STG;
        __syncthreads();                 // stage st free (ldmatrix of c-2 done)
        // ---- STS X (coalesced, swizzled rows of 128B) ----
#pragma unroll
        for (int m = 0; m < 8; m++) {
            const uint32_t boff = SWZ((uint32_t)((rbase + 2 * m) * 128 + f4 * 8));
            *(uint2*)(sb + OFF_AHI + boff) = xh2[m];
            *(uint2*)(sb + OFF_ALO + boff) = xl2[m];
        }
        // ---- cp.async W chunk (L2-hot) -> smem B tiles, warp-contiguous ----
        {
            const char* sH = wsrcH + c * 32768;
            const char* sL = wsrcL + c * 32768;
#pragma unroll
            for (int m = 0; m < 8; m++) {
                uint32_t o = (uint32_t)(m * 4096 + t * 16);
                CP_ASYNC16(sbb + OFF_BHI + o, sH + o);
                CP_ASYNC16(sbb + OFF_BLO + o, sL + o);
            }
            CP_COMMIT();
        }
        // ---- overlap: build next chunk's X while cp.async lands ----
        if (c + 1 < NCH) buildX(c + 1);
        CP_WAIT0();
        __syncthreads();
        // ---- MMA over stage st ----
        const uint32_t sAhi = sbb + OFF_AHI, sAlo = sbb + OFF_ALO;
        const uint32_t sBhi = sbb + OFF_BHI, sBlo = sbb + OFF_BLO;
#pragma unroll
        for (int ks = 0; ks < 4; ks++) {
            const uint32_t kbase = ks * 32 + kbL;
            uint32_t ah[4][4], al[4][4];
#pragma unroll
            for (int mt = 0; mt < 4; mt++) {
                uint32_t off = SWZ((aRow + mt * 16) * 128 + kbase);
                ldsm4(ah[mt], sAhi + off);
                ldsm4(al[mt], sAlo + off);
            }
#pragma unroll
            for (int nh = 0; nh < 2; nh++) {
                uint32_t bh[2][4], bl[2][4];
#pragma unroll
                for (int p = 0; p < 2; p++) {
                    uint32_t off = SWZ((nRow + nh * 32 + p * 16) * 128 + kbase);
                    ldsm4(bh[p], sBhi + off);
                    ldsm4(bl[p], sBlo + off);
                }
#pragma unroll
                for (int mt = 0; mt < 4; mt++)
#pragma unroll
                    for (int p = 0; p < 2; p++)
#pragma unroll
                        for (int e = 0; e < 2; e++) {
                            float* d = acc[mt][nh * 4 + p * 2 + e];
                            mma16816(d, ah[mt], bh[p][e], bh[p][e + 2]);
                            mma16816(d, ah[mt], bl[p][e], bl[p][e + 2]);
                            mma16816(d, al[mt], bh[p][e], bh[p][e + 2]);
                        }
            }
        }
    }

    // ---- epilogue: bias, relu, dot w2 ----
    // D frag: rows wm*64+mt*16+(lane>>2) and +8; cols wn*64+nt*8+(lane&3)*2+{0,1}
#pragma unroll
    for (int mt = 0; mt < 4; mt++) {
        float ps0 = 0.f, ps1 = 0.f;
#pragma unroll
        for (int nt = 0; nt < 8; nt++) {
            int h = wn * 64 + nt * 8 + (lane & 3) * 2;
            float b0 = s_b1[h],  w0 = s_w2[h];
            float b1v = s_b1[h + 1], w1v = s_w2[h + 1];
            ps0 = fmaf(fmaxf(acc[mt][nt][0] + b0, 0.f),  w0,  ps0);
            ps0 = fmaf(fmaxf(acc[mt][nt][1] + b1v, 0.f), w1v, ps0);
            ps1 = fmaf(fmaxf(acc[mt][nt][2] + b0, 0.f),  w0,  ps1);
            ps1 = fmaf(fmaxf(acc[mt][nt][3] + b1v, 0.f), w1v, ps1);
        }
        ps0 += __shfl_xor_sync(0xffffffffu, ps0, 1);
        ps0 += __shfl_xor_sync(0xffffffffu, ps0, 2);
        ps1 += __shfl_xor_sync(0xffffffffu, ps1, 1);
        ps1 += __shfl_xor_sync(0xffffffffu, ps1, 2);
        if ((lane & 3) == 0) {
            int r0 = wm * 64 + mt * 16 + (lane >> 2);
            red[r0][wn] = ps0;
            red[r0 + 8][wn] = ps1;
        }
    }
    __syncthreads();
    if (t < 128) rowlogit[t] = red[t][0] + red[t][1] + red[t][2] + red[t][3];
    __syncthreads();
    if (PHASE == 0) {
        if (t < 16) {
            float s = 0.f;
#pragma unroll
            for (int r = 0; r < 8; r++) s += rowlogit[t * 8 + r];
            outv[blockIdx.x * 16 + t] = s * 0.125f + b2[0];
        }
    } else {
        if (t < 128) outv[blockIdx.x * 128 + t] = rowlogit[t] + b2[0];
    }
}

// ---------------------------------------------------------------- top-64
// Register-resident iterative selection: tie semantics = value desc, index asc.
// Ordering by logit == ordering by sigmoid(logit); masked entries -> -inf.
__global__ __launch_bounds__(1024) void topk_kernel(const float* __restrict__ logits,
                                                    const float* __restrict__ mask,
                                                    float* __restrict__ out_inds) {
    const int t = threadIdx.x;
    const int wid = t >> 5, lane = t & 31;
    float v[16];
#pragma unroll
    for (int u = 0; u < 16; u++) {
        int p = u * 1024 + t;
        v[u] = (mask[p] != 0.f) ? logits[p] : -3.4e38f;
    }
    float lmax = -3.4e38f; int ls = 0;
#pragma unroll
    for (int u = 0; u < 16; u++) if (v[u] > lmax) { lmax = v[u]; ls = u; }

    __shared__ float wv[32];
    __shared__ int wi2[32];
    __shared__ int s_best;
    for (int sel = 0; sel < KTOP; sel++) {
        float bv = lmax;
        int bi = ls * 1024 + t;
#pragma unroll
        for (int o = 16; o > 0; o >>= 1) {
            float ov = __shfl_down_sync(0xffffffffu, bv, o);
            int oi = __shfl_down_sync(0xffffffffu, bi, o);
            if (ov > bv || (ov == bv && oi < bi)) { bv = ov; bi = oi; }
        }
        if (lane == 0) { wv[wid] = bv; wi2[wid] = bi; }
        __syncthreads();
        if (wid == 0) {
            bv = wv[lane]; bi = wi2[lane];
#pragma unroll
            for (int o = 16; o > 0; o >>= 1) {
                float ov = __shfl_down_sync(0xffffffffu, bv, o);
                int oi = __shfl_down_sync(0xffffffffu, bi, o);
                if (ov > bv || (ov == bv && oi < bi)) { bv = ov; bi = oi; }
            }
            if (lane == 0) { g_topk[sel] = bi; out_inds[sel] = (float)bi; s_best = bi; }
        }
        __syncthreads();
        int w = s_best;
        if ((w & 1023) == t) {
            v[w >> 10] = -3.4e38f;
            lmax = -3.4e38f; ls = 0;
#pragma unroll
            for (int u = 0; u < 16; u++) if (v[u] > lmax) { lmax = v[u]; ls = u; }
        }
    }
}

// ---------------------------------------------------------------- gather
__global__ void gather_pf_kernel(const float* __restrict__ obj,
                                 const float* __restrict__ geo) {
    const int b = blockIdx.x;
    const int ind = g_topk[b];
    const int i = ind >> 7, j = ind & 127;
    const int d = threadIdx.x * 4;
    float4 a = make_float4(0.f, 0.f, 0.f, 0.f);
#pragma unroll
    for (int r = 0; r < RR; r++) {
        const float4 oi = *(const float4*)&obj[(size_t)(r * NN + i) * DD + d];
        const float4 oj = *(const float4*)&obj[(size_t)(r * NN + j) * DD + d];
        const float4 g4 = *(const float4*)&geo[(size_t)((r * NN + i) * NN + j) * DD + d];
        a.x += fmaf(oi.x, oj.x, g4.x);
        a.y += fmaf(oi.y, oj.y, g4.y);
        a.z += fmaf(oi.z, oj.z, g4.z);
        a.w += fmaf(oi.w, oj.w, g4.w);
    }
    a.x *= (1.f / RR); a.y *= (1.f / RR); a.z *= (1.f / RR); a.w *= (1.f / RR);
    *(float4*)&g_pf[b * DD + d] = a;
}

// ---------------------------------------------------------------- launch
extern "C" void kernel_launch(void* const* d_in, const int* in_sizes, int n_in,
                              void* d_out, int out_size) {
    const float* obj  = (const float*)d_in[0];
    const float* geo  = (const float*)d_in[1];
    const float* mask = (const float*)d_in[2];
    const float* w1a  = (const float*)d_in[3];
    const float* b1a  = (const float*)d_in[4];
    const float* w2a  = (const float*)d_in[5];
    const float* b2a  = (const float*)d_in[6];
    const float* w1b  = (const float*)d_in[7];
    const float* b1b  = (const float*)d_in[8];
    const float* w2b  = (const float*)d_in[9];
    const float* b2b  = (const float*)d_in[10];
    float* out = (float*)d_out;

    const int dyn = 2 * STG + 1024;  // +1024 for manual alignment
    cudaFuncSetAttribute(gemm_mlp_kernel<0>,
                         cudaFuncAttributeMaxDynamicSharedMemorySize, dyn);
    cudaFuncSetAttribute(gemm_mlp_kernel<1>,
                         cudaFuncAttributeMaxDynamicSharedMemorySize, dyn);

    prep_w_kernel<<<1024, 256>>>(w1a, w1b);
    gemm_mlp_kernel<0><<<NPAIR / 16, 256, dyn>>>(obj, geo, b1a, w2a, b2a, out);
    topk_kernel<<<1, 1024>>>(out, mask, out + NPAIR + KTOP * KTOP);
    gather_pf_kernel<<<KTOP, 128>>>(obj, geo);
    gemm_mlp_kernel<1><<<KTOP * KTOP / 128, 256, dyn>>>(obj, geo, b1b, w2b, b2b,
                                                        out + NPAIR);
}

// round 7
// speedup vs baseline: 2.3646x; 1.0121x over previous
#include <cuda_runtime.h>
#include <cuda_bf16.h>
#include <cstdint>
#include <math.h>

// ---------------------------------------------------------------- constants
#define RR 8
#define NN 128
#define DD 512
#define HH 256
#define KTOP 64
#define NPAIR (NN*NN)          // 16384
#define KC 64                  // K per chunk (64 bf16 = 128B rows, SW128 atom)
#define NCH 8                  // 512 / 64
#define STG 98304              // bytes per smem stage (A_hi+A_lo+B_hi+B_lo)
#define OFF_AHI 0
#define OFF_ALO 16384
#define OFF_BHI 32768
#define OFF_BLO 65536
#define SWZ(o) ((o) ^ (((o) >> 3) & 0x70))

// ---------------------------------------------------------------- scratch
__device__ float g_pf[KTOP * DD];                     // gathered mean pair feats
__device__ int   g_topk[KTOP];
__device__ __align__(16) __nv_bfloat16 g_whi[2][NCH * 16384]; // pre-split W (hi)
__device__ __align__(16) __nv_bfloat16 g_wlo[2][NCH * 16384]; // pre-split W (lo)

// ---------------------------------------------------------------- helpers
static __device__ __forceinline__ uint32_t smem_u32(const void* p) {
    uint32_t a;
    asm("{ .reg .u64 t; cvta.to.shared.u64 t, %1; cvt.u32.u64 %0, t; }"
        : "=r"(a) : "l"(p));
    return a;
}
static __device__ __forceinline__ void ldsm4(uint32_t* r, uint32_t addr) {
    asm volatile("ldmatrix.sync.aligned.m8n8.x4.shared.b16 {%0,%1,%2,%3}, [%4];"
                 : "=r"(r[0]), "=r"(r[1]), "=r"(r[2]), "=r"(r[3]) : "r"(addr));
}
static __device__ __forceinline__ void mma16816(float* d, const uint32_t* a,
                                                uint32_t b0, uint32_t b1) {
    asm volatile(
        "mma.sync.aligned.m16n8k16.row.col.f32.bf16.bf16.f32 "
        "{%0,%1,%2,%3}, {%4,%5,%6,%7}, {%8,%9}, {%0,%1,%2,%3};"
        : "+f"(d[0]), "+f"(d[1]), "+f"(d[2]), "+f"(d[3])
        : "r"(a[0]), "r"(a[1]), "r"(a[2]), "r"(a[3]), "r"(b0), "r"(b1));
}
#define CP_ASYNC16(dst, src) \
    asm volatile("cp.async.cg.shared.global [%0], [%1], 16;" \
                 :: "r"(dst), "l"(src) : "memory")
#define CP_COMMIT() asm volatile("cp.async.commit_group;" ::: "memory")
#define CP_WAIT0()  asm volatile("cp.async.wait_group 0;" ::: "memory")
#define CP_WAIT1()  asm volatile("cp.async.wait_group 1;" ::: "memory")

// split one float pair into packed bf16 hi (returned) + residuals
static __device__ __forceinline__ uint32_t pkhi(float a, float b,
                                                float& ra, float& rb) {
    __nv_bfloat16 ha = __float2bfloat16(a), hb = __float2bfloat16(b);
    ra = a - __bfloat162float(ha);
    rb = b - __bfloat162float(hb);
    __nv_bfloat162 h2 = __halves2bfloat162(ha, hb);
    return *reinterpret_cast<uint32_t*>(&h2);
}
static __device__ __forceinline__ uint32_t pklo(float a, float b) {
    __nv_bfloat162 h2 = __floats2bfloat162_rn(a, b);
    return *reinterpret_cast<uint32_t*>(&h2);
}

// ---------------------------------------------------------------- W prep
__global__ void prep_w_kernel(const float* __restrict__ w1a,
                              const float* __restrict__ w1b) {
    int idx = blockIdx.x * 256 + threadIdx.x;      // 0..262143
    int arr = idx >> 17;
    int rem = idx & 131071;
    int c  = rem >> 14;
    int n  = (rem >> 6) & 255;
    int kk = rem & 63;
    const float* w = arr ? w1b : w1a;
    float f = w[(size_t)(c * 64 + kk) * HH + n];
    __nv_bfloat16 hi = __float2bfloat16(f);
    __nv_bfloat16 lo = __float2bfloat16(f - __bfloat162float(hi));
    uint32_t off = (uint32_t)c * 32768u + SWZ((uint32_t)(n * 128 + kk * 2));
    *(__nv_bfloat16*)((char*)g_whi[arr] + off) = hi;
    *(__nv_bfloat16*)((char*)g_wlo[arr] + off) = lo;
}

// ---------------------------------------------------------------- fused GEMM
// Pipelined mainloop: while MMA(c) runs, cp.async(c+1) is in flight and
// buildX(c+2)'s LDGs issue behind the MMA drain.  2 barriers/chunk.
template <int PHASE>
__global__ __launch_bounds__(256, 1)
void gemm_mlp_kernel(const float* __restrict__ obj, const float* __restrict__ geo,
                     const float* __restrict__ b1, const float* __restrict__ w2,
                     const float* __restrict__ b2, float* __restrict__ outv) {
    extern __shared__ char smraw[];
    char* sm = (char*)(((uintptr_t)smraw + 1023) & ~(uintptr_t)1023);
    __shared__ float s_b1[HH], s_w2[HH];
    __shared__ float red[128][5];
    __shared__ float rowlogit[128];

    const int t = threadIdx.x;
    const int wid = t >> 5, lane = t & 31;
    const int wm = wid >> 2;           // 0..1  (M warp)
    const int wn = wid & 3;            // 0..3  (N warp)
    const uint32_t smb = smem_u32(sm);

    s_b1[t] = b1[t];
    s_w2[t] = w2[t];

    const char* wsrcH = (const char*)g_whi[PHASE];
    const char* wsrcL = (const char*)g_wlo[PHASE];

    // X-build ownership: warp w -> rows 16w..16w+15 (2 rows/iter, coalesced)
    const int rbase = (wid << 4) + (lane >> 4);
    const int f4    = lane & 15;

    float acc[4][8][4];
#pragma unroll
    for (int a = 0; a < 4; a++)
#pragma unroll
        for (int b = 0; b < 8; b++)
#pragma unroll
            for (int cq = 0; cq < 4; cq++) acc[a][b][cq] = 0.f;

    uint2 xh2[8], xl2[8];
    auto buildX = [&](int c) {
#pragma unroll
        for (int m = 0; m < 8; m++) {
            const int row = rbase + 2 * m;
            float4 x;
            if (PHASE == 0) {
                int pl = row >> 3, r = row & 7;
                int p = blockIdx.x * 16 + pl;
                int i = p >> 7, j = p & 127;
                const float4 a = *(const float4*)(obj + (size_t)(r * NN + i) * DD
                                                  + c * KC + f4 * 4);
                const float4 b = *(const float4*)(obj + (size_t)(r * NN + j) * DD
                                                  + c * KC + f4 * 4);
                const float4 g4 = *(const float4*)(geo
                    + (size_t)((r * NN + i) * NN + j) * DD + c * KC + f4 * 4);
                x.x = fmaf(a.x, b.x, g4.x);
                x.y = fmaf(a.y, b.y, g4.y);
                x.z = fmaf(a.z, b.z, g4.z);
                x.w = fmaf(a.w, b.w, g4.w);
            } else {
                int g = blockIdx.x * 128 + row;
                const float4 a = *(const float4*)(g_pf + (g >> 6) * DD
                                                  + c * KC + f4 * 4);
                const float4 b = *(const float4*)(g_pf + (g & 63) * DD
                                                  + c * KC + f4 * 4);
                x.x = a.x * b.x; x.y = a.y * b.y;
                x.z = a.z * b.z; x.w = a.w * b.w;
            }
            float r0, r1, r2, r3;
            xh2[m].x = pkhi(x.x, x.y, r0, r1);
            xh2[m].y = pkhi(x.z, x.w, r2, r3);
            xl2[m].x = pklo(r0, r1);
            xl2[m].y = pklo(r2, r3);
        }
    };
    // STS chunk regs into buffer bs, then cp.async W chunk c into it
    auto stageStore = [&](char* bs, uint32_t bsb, int c) {
#pragma unroll
        for (int m = 0; m < 8; m++) {
            const uint32_t boff = SWZ((uint32_t)((rbase + 2 * m) * 128 + f4 * 8));
            *(uint2*)(bs + OFF_AHI + boff) = xh2[m];
            *(uint2*)(bs + OFF_ALO + boff) = xl2[m];
        }
        const char* sH = wsrcH + c * 32768;
        const char* sL = wsrcL + c * 32768;
#pragma unroll
        for (int m = 0; m < 8; m++) {
            uint32_t o = (uint32_t)(m * 4096 + t * 16);
            CP_ASYNC16(bsb + OFF_BHI + o, sH + o);
            CP_ASYNC16(bsb + OFF_BLO + o, sL + o);
        }
        CP_COMMIT();
    };

    // lane-level ldmatrix address components
    const uint32_t aRow = (uint32_t)(wm * 64 + (lane & 15));
    const uint32_t nRow = (uint32_t)(wn * 64 + (lane & 15));
    const uint32_t kbL  = (uint32_t)((lane >> 4) * 16);

    // ---- prologue: chunk 0 staged, chunk 1 built in regs ----
    buildX(0);
    stageStore(sm, smb, 0);
    buildX(1);

#pragma unroll 1
    for (int c = 0; c < NCH; c++) {
        const int st = c & 1;
        const uint32_t sbb = smb + st * STG;
        // stage chunk c+1 into the other buffer (free since MMA(c-1) +
        // end-of-iter barrier); its cp.async flies during MMA(c)
        if (c + 1 < NCH) {
            stageStore(sm + (st ^ 1) * STG, smb + (st ^ 1) * STG, c + 1);
            CP_WAIT1();          // group c landed; group c+1 may fly
        } else {
            CP_WAIT0();
        }
        __syncthreads();         // STS(c) + cp(c) visible to all warps
        // ---- MMA over stage st ----
        const uint32_t sAhi = sbb + OFF_AHI, sAlo = sbb + OFF_ALO;
        const uint32_t sBhi = sbb + OFF_BHI, sBlo = sbb + OFF_BLO;
#pragma unroll
        for (int ks = 0; ks < 4; ks++) {
            const uint32_t kbase = ks * 32 + kbL;
            uint32_t ah[4][4], al[4][4];
#pragma unroll
            for (int mt = 0; mt < 4; mt++) {
                uint32_t off = SWZ((aRow + mt * 16) * 128 + kbase);
                ldsm4(ah[mt], sAhi + off);
                ldsm4(al[mt], sAlo + off);
            }
#pragma unroll
            for (int nh = 0; nh < 2; nh++) {
                uint32_t bh[2][4], bl[2][4];
#pragma unroll
                for (int p = 0; p < 2; p++) {
                    uint32_t off = SWZ((nRow + nh * 32 + p * 16) * 128 + kbase);
                    ldsm4(bh[p], sBhi + off);
                    ldsm4(bl[p], sBlo + off);
                }
#pragma unroll
                for (int mt = 0; mt < 4; mt++)
#pragma unroll
                    for (int p = 0; p < 2; p++)
#pragma unroll
                        for (int e = 0; e < 2; e++) {
                            float* d = acc[mt][nh * 4 + p * 2 + e];
                            mma16816(d, ah[mt], bh[p][e], bh[p][e + 2]);
                            mma16816(d, ah[mt], bl[p][e], bl[p][e + 2]);
                            mma16816(d, al[mt], bh[p][e], bh[p][e + 2]);
                        }
            }
        }
        // LDGs for chunk c+2 issue behind the MMA drain, consumed next iter
        if (c + 2 < NCH) buildX(c + 2);
        __syncthreads();         // all warps done reading stage st
    }

    // ---- epilogue: bias, relu, dot w2 ----
#pragma unroll
    for (int mt = 0; mt < 4; mt++) {
        float ps0 = 0.f, ps1 = 0.f;
#pragma unroll
        for (int nt = 0; nt < 8; nt++) {
            int h = wn * 64 + nt * 8 + (lane & 3) * 2;
            float b0 = s_b1[h],  w0 = s_w2[h];
            float b1v = s_b1[h + 1], w1v = s_w2[h + 1];
            ps0 = fmaf(fmaxf(acc[mt][nt][0] + b0, 0.f),  w0,  ps0);
            ps0 = fmaf(fmaxf(acc[mt][nt][1] + b1v, 0.f), w1v, ps0);
            ps1 = fmaf(fmaxf(acc[mt][nt][2] + b0, 0.f),  w0,  ps1);
            ps1 = fmaf(fmaxf(acc[mt][nt][3] + b1v, 0.f), w1v, ps1);
        }
        ps0 += __shfl_xor_sync(0xffffffffu, ps0, 1);
        ps0 += __shfl_xor_sync(0xffffffffu, ps0, 2);
        ps1 += __shfl_xor_sync(0xffffffffu, ps1, 1);
        ps1 += __shfl_xor_sync(0xffffffffu, ps1, 2);
        if ((lane & 3) == 0) {
            int r0 = wm * 64 + mt * 16 + (lane >> 2);
            red[r0][wn] = ps0;
            red[r0 + 8][wn] = ps1;
        }
    }
    __syncthreads();
    if (t < 128) rowlogit[t] = red[t][0] + red[t][1] + red[t][2] + red[t][3];
    __syncthreads();
    if (PHASE == 0) {
        if (t < 16) {
            float s = 0.f;
#pragma unroll
            for (int r = 0; r < 8; r++) s += rowlogit[t * 8 + r];
            outv[blockIdx.x * 16 + t] = s * 0.125f + b2[0];
        }
    } else {
        if (t < 128) outv[blockIdx.x * 128 + t] = rowlogit[t] + b2[0];
    }
}

// ---------------------------------------------------------------- top-64
__global__ __launch_bounds__(1024) void topk_kernel(const float* __restrict__ logits,
                                                    const float* __restrict__ mask,
                                                    float* __restrict__ out_inds) {
    const int t = threadIdx.x;
    const int wid = t >> 5, lane = t & 31;
    float v[16];
#pragma unroll
    for (int u = 0; u < 16; u++) {
        int p = u * 1024 + t;
        v[u] = (mask[p] != 0.f) ? logits[p] : -3.4e38f;
    }
    float lmax = -3.4e38f; int ls = 0;
#pragma unroll
    for (int u = 0; u < 16; u++) if (v[u] > lmax) { lmax = v[u]; ls = u; }

    __shared__ float wv[32];
    __shared__ int wi2[32];
    __shared__ int s_best;
    for (int sel = 0; sel < KTOP; sel++) {
        float bv = lmax;
        int bi = ls * 1024 + t;
#pragma unroll
        for (int o = 16; o > 0; o >>= 1) {
            float ov = __shfl_down_sync(0xffffffffu, bv, o);
            int oi = __shfl_down_sync(0xffffffffu, bi, o);
            if (ov > bv || (ov == bv && oi < bi)) { bv = ov; bi = oi; }
        }
        if (lane == 0) { wv[wid] = bv; wi2[wid] = bi; }
        __syncthreads();
        if (wid == 0) {
            bv = wv[lane]; bi = wi2[lane];
#pragma unroll
            for (int o = 16; o > 0; o >>= 1) {
                float ov = __shfl_down_sync(0xffffffffu, bv, o);
                int oi = __shfl_down_sync(0xffffffffu, bi, o);
                if (ov > bv || (ov == bv && oi < bi)) { bv = ov; bi = oi; }
            }
            if (lane == 0) { g_topk[sel] = bi; out_inds[sel] = (float)bi; s_best = bi; }
        }
        __syncthreads();
        int w = s_best;
        if ((w & 1023) == t) {
            v[w >> 10] = -3.4e38f;
            lmax = -3.4e38f; ls = 0;
#pragma unroll
            for (int u = 0; u < 16; u++) if (v[u] > lmax) { lmax = v[u]; ls = u; }
        }
    }
}

// ---------------------------------------------------------------- gather
__global__ void gather_pf_kernel(const float* __restrict__ obj,
                                 const float* __restrict__ geo) {
    const int b = blockIdx.x;
    const int ind = g_topk[b];
    const int i = ind >> 7, j = ind & 127;
    const int d = threadIdx.x * 4;
    float4 a = make_float4(0.f, 0.f, 0.f, 0.f);
#pragma unroll
    for (int r = 0; r < RR; r++) {
        const float4 oi = *(const float4*)&obj[(size_t)(r * NN + i) * DD + d];
        const float4 oj = *(const float4*)&obj[(size_t)(r * NN + j) * DD + d];
        const float4 g4 = *(const float4*)&geo[(size_t)((r * NN + i) * NN + j) * DD + d];
        a.x += fmaf(oi.x, oj.x, g4.x);
        a.y += fmaf(oi.y, oj.y, g4.y);
        a.z += fmaf(oi.z, oj.z, g4.z);
        a.w += fmaf(oi.w, oj.w, g4.w);
    }
    a.x *= (1.f / RR); a.y *= (1.f / RR); a.z *= (1.f / RR); a.w *= (1.f / RR);
    *(float4*)&g_pf[b * DD + d] = a;
}

// ---------------------------------------------------------------- launch
extern "C" void kernel_launch(void* const* d_in, const int* in_sizes, int n_in,
                              void* d_out, int out_size) {
    const float* obj  = (const float*)d_in[0];
    const float* geo  = (const float*)d_in[1];
    const float* mask = (const float*)d_in[2];
    const float* w1a  = (const float*)d_in[3];
    const float* b1a  = (const float*)d_in[4];
    const float* w2a  = (const float*)d_in[5];
    const float* b2a  = (const float*)d_in[6];
    const float* w1b  = (const float*)d_in[7];
    const float* b1b  = (const float*)d_in[8];
    const float* w2b  = (const float*)d_in[9];
    const float* b2b  = (const float*)d_in[10];
    float* out = (float*)d_out;

    const int dyn = 2 * STG + 1024;  // +1024 for manual alignment
    cudaFuncSetAttribute(gemm_mlp_kernel<0>,
                         cudaFuncAttributeMaxDynamicSharedMemorySize, dyn);
    cudaFuncSetAttribute(gemm_mlp_kernel<1>,
                         cudaFuncAttributeMaxDynamicSharedMemorySize, dyn);

    prep_w_kernel<<<1024, 256>>>(w1a, w1b);
    gemm_mlp_kernel<0><<<NPAIR / 16, 256, dyn>>>(obj, geo, b1a, w2a, b2a, out);
    topk_kernel<<<1, 1024>>>(out, mask, out + NPAIR + KTOP * KTOP);
    gather_pf_kernel<<<KTOP, 128>>>(obj, geo);
    gemm_mlp_kernel<1><<<KTOP * KTOP / 128, 256, dyn>>>(obj, geo, b1b, w2b, b2b,
                                                        out + NPAIR);
}

// round 8
// speedup vs baseline: 2.3854x; 1.0088x over previous
#include <cuda_runtime.h>
#include <cuda_bf16.h>
#include <cstdint>
#include <math.h>

// ---------------------------------------------------------------- constants
#define RR 8
#define NN 128
#define DD 512
#define HH 256
#define KTOP 64
#define NPAIR (NN*NN)          // 16384
#define KC 64                  // K per chunk (64 bf16 = 128B rows, SW128 atom)
#define NCH 8                  // 512 / 64
#define STG 98304              // bytes per smem stage (A_hi+A_lo+B_hi+B_lo)
#define OFF_AHI 0
#define OFF_ALO 16384
#define OFF_BHI 32768
#define OFF_BLO 65536
#define SWZ(o) ((o) ^ (((o) >> 3) & 0x70))

// ---------------------------------------------------------------- scratch
__device__ float g_pf[KTOP * DD];                     // gathered mean pair feats
__device__ int   g_topk[KTOP];
__device__ __align__(16) __nv_bfloat16 g_whi[2][NCH * 16384]; // pre-split W (hi)
__device__ __align__(16) __nv_bfloat16 g_wlo[2][NCH * 16384]; // pre-split W (lo)

// ---------------------------------------------------------------- helpers
static __device__ __forceinline__ uint32_t smem_u32(const void* p) {
    uint32_t a;
    asm("{ .reg .u64 t; cvta.to.shared.u64 t, %1; cvt.u32.u64 %0, t; }"
        : "=r"(a) : "l"(p));
    return a;
}
static __device__ __forceinline__ void ldsm4(uint32_t* r, uint32_t addr) {
    asm volatile("ldmatrix.sync.aligned.m8n8.x4.shared.b16 {%0,%1,%2,%3}, [%4];"
                 : "=r"(r[0]), "=r"(r[1]), "=r"(r[2]), "=r"(r[3]) : "r"(addr));
}
static __device__ __forceinline__ void mma16816(float* d, const uint32_t* a,
                                                uint32_t b0, uint32_t b1) {
    asm volatile(
        "mma.sync.aligned.m16n8k16.row.col.f32.bf16.bf16.f32 "
        "{%0,%1,%2,%3}, {%4,%5,%6,%7}, {%8,%9}, {%0,%1,%2,%3};"
        : "+f"(d[0]), "+f"(d[1]), "+f"(d[2]), "+f"(d[3])
        : "r"(a[0]), "r"(a[1]), "r"(a[2]), "r"(a[3]), "r"(b0), "r"(b1));
}
#define CP_ASYNC16(dst, src) \
    asm volatile("cp.async.cg.shared.global [%0], [%1], 16;" \
                 :: "r"(dst), "l"(src) : "memory")
#define CP_COMMIT() asm volatile("cp.async.commit_group;" ::: "memory")
#define CP_WAIT0()  asm volatile("cp.async.wait_group 0;" ::: "memory")
#define CP_WAIT1()  asm volatile("cp.async.wait_group 1;" ::: "memory")

// split one float pair into packed bf16 hi (returned) + residuals
static __device__ __forceinline__ uint32_t pkhi(float a, float b,
                                                float& ra, float& rb) {
    __nv_bfloat16 ha = __float2bfloat16(a), hb = __float2bfloat16(b);
    ra = a - __bfloat162float(ha);
    rb = b - __bfloat162float(hb);
    __nv_bfloat162 h2 = __halves2bfloat162(ha, hb);
    return *reinterpret_cast<uint32_t*>(&h2);
}
static __device__ __forceinline__ uint32_t pklo(float a, float b) {
    __nv_bfloat162 h2 = __floats2bfloat162_rn(a, b);
    return *reinterpret_cast<uint32_t*>(&h2);
}

// ---------------------------------------------------------------- W prep
__global__ void prep_w_kernel(const float* __restrict__ w1a,
                              const float* __restrict__ w1b) {
    int idx = blockIdx.x * 256 + threadIdx.x;      // 0..262143
    int arr = idx >> 17;
    int rem = idx & 131071;
    int c  = rem >> 14;
    int n  = (rem >> 6) & 255;
    int kk = rem & 63;
    const float* w = arr ? w1b : w1a;
    float f = w[(size_t)(c * 64 + kk) * HH + n];
    __nv_bfloat16 hi = __float2bfloat16(f);
    __nv_bfloat16 lo = __float2bfloat16(f - __bfloat162float(hi));
    uint32_t off = (uint32_t)c * 32768u + SWZ((uint32_t)(n * 128 + kk * 2));
    *(__nv_bfloat16*)((char*)g_whi[arr] + off) = hi;
    *(__nv_bfloat16*)((char*)g_wlo[arr] + off) = lo;
}

// ---------------------------------------------------------------- fused GEMM
// 512 threads, 16 warps: warp grid 4(M) x 4(N), warp tile 32x64.
// CTA tile M=128, N=256, K chunked at 64, double-buffered smem.
// acc = hi*hi + hi*lo + lo*hi  (bf16x3 split, fp32 accumulate).
template <int PHASE>
__global__ __launch_bounds__(512, 1)
void gemm_mlp_kernel(const float* __restrict__ obj, const float* __restrict__ geo,
                     const float* __restrict__ b1, const float* __restrict__ w2,
                     const float* __restrict__ b2, float* __restrict__ outv) {
    extern __shared__ char smraw[];
    char* sm = (char*)(((uintptr_t)smraw + 1023) & ~(uintptr_t)1023);
    __shared__ float s_b1[HH], s_w2[HH];
    __shared__ float red[128][5];
    __shared__ float rowlogit[128];

    const int t = threadIdx.x;
    const int wid = t >> 5, lane = t & 31;
    const int wm = wid >> 2;           // 0..3  (M warp)
    const int wn = wid & 3;            // 0..3  (N warp)
    const uint32_t smb = smem_u32(sm);

    if (t < HH) { s_b1[t] = b1[t]; s_w2[t] = w2[t]; }

    const char* wsrcH = (const char*)g_whi[PHASE];
    const char* wsrcL = (const char*)g_wlo[PHASE];

    // X-build: per iter m (0..3), thread covers row = m*32 + (t>>4), f4 = t&15
    const int rsub = t >> 4;          // 0..31
    const int f4   = t & 15;

    float acc[2][8][4];
#pragma unroll
    for (int a = 0; a < 2; a++)
#pragma unroll
        for (int b = 0; b < 8; b++)
#pragma unroll
            for (int cq = 0; cq < 4; cq++) acc[a][b][cq] = 0.f;

    uint2 xh2[4], xl2[4];
    auto buildX = [&](int c) {
#pragma unroll
        for (int m = 0; m < 4; m++) {
            const int row = m * 32 + rsub;
            float4 x;
            if (PHASE == 0) {
                int pl = row >> 3, r = row & 7;
                int p = blockIdx.x * 16 + pl;
                int i = p >> 7, j = p & 127;
                const float4 a = *(const float4*)(obj + (size_t)(r * NN + i) * DD
                                                  + c * KC + f4 * 4);
                const float4 b = *(const float4*)(obj + (size_t)(r * NN + j) * DD
                                                  + c * KC + f4 * 4);
                const float4 g4 = *(const float4*)(geo
                    + (size_t)((r * NN + i) * NN + j) * DD + c * KC + f4 * 4);
                x.x = fmaf(a.x, b.x, g4.x);
                x.y = fmaf(a.y, b.y, g4.y);
                x.z = fmaf(a.z, b.z, g4.z);
                x.w = fmaf(a.w, b.w, g4.w);
            } else {
                int g = blockIdx.x * 128 + row;
                const float4 a = *(const float4*)(g_pf + (g >> 6) * DD
                                                  + c * KC + f4 * 4);
                const float4 b = *(const float4*)(g_pf + (g & 63) * DD
                                                  + c * KC + f4 * 4);
                x.x = a.x * b.x; x.y = a.y * b.y;
                x.z = a.z * b.z; x.w = a.w * b.w;
            }
            float r0, r1, r2, r3;
            xh2[m].x = pkhi(x.x, x.y, r0, r1);
            xh2[m].y = pkhi(x.z, x.w, r2, r3);
            xl2[m].x = pklo(r0, r1);
            xl2[m].y = pklo(r2, r3);
        }
    };
    // STS chunk regs into buffer bs, then cp.async W chunk c into it
    auto stageStore = [&](char* bs, uint32_t bsb, int c) {
#pragma unroll
        for (int m = 0; m < 4; m++) {
            const uint32_t boff = SWZ((uint32_t)((m * 32 + rsub) * 128 + f4 * 8));
            *(uint2*)(bs + OFF_AHI + boff) = xh2[m];
            *(uint2*)(bs + OFF_ALO + boff) = xl2[m];
        }
        const char* sH = wsrcH + c * 32768;
        const char* sL = wsrcL + c * 32768;
#pragma unroll
        for (int m = 0; m < 4; m++) {
            uint32_t o = (uint32_t)(m * 8192 + t * 16);
            CP_ASYNC16(bsb + OFF_BHI + o, sH + o);
            CP_ASYNC16(bsb + OFF_BLO + o, sL + o);
        }
        CP_COMMIT();
    };

    // lane-level ldmatrix address components
    const uint32_t aRow = (uint32_t)(wm * 32 + (lane & 15));
    const uint32_t nRow = (uint32_t)(wn * 64 + (lane & 15));
    const uint32_t kbL  = (uint32_t)((lane >> 4) * 16);

    // ---- prologue: chunk 0 staged, chunk 1 built in regs ----
    buildX(0);
    stageStore(sm, smb, 0);
    buildX(1);

#pragma unroll 1
    for (int c = 0; c < NCH; c++) {
        const int st = c & 1;
        const uint32_t sbb = smb + st * STG;
        // stage chunk c+1 into the other buffer; its cp.async flies during MMA(c)
        if (c + 1 < NCH) {
            stageStore(sm + (st ^ 1) * STG, smb + (st ^ 1) * STG, c + 1);
            CP_WAIT1();          // group c landed; group c+1 may fly
        } else {
            CP_WAIT0();
        }
        __syncthreads();         // STS(c) + cp(c) visible to all warps
        // ---- MMA over stage st ----
        const uint32_t sAhi = sbb + OFF_AHI, sAlo = sbb + OFF_ALO;
        const uint32_t sBhi = sbb + OFF_BHI, sBlo = sbb + OFF_BLO;
#pragma unroll
        for (int ks = 0; ks < 4; ks++) {
            const uint32_t kbase = ks * 32 + kbL;
            uint32_t ah[2][4], al[2][4];
#pragma unroll
            for (int mt = 0; mt < 2; mt++) {
                uint32_t off = SWZ((aRow + mt * 16) * 128 + kbase);
                ldsm4(ah[mt], sAhi + off);
                ldsm4(al[mt], sAlo + off);
            }
#pragma unroll
            for (int nh = 0; nh < 2; nh++) {
                uint32_t bh[2][4], bl[2][4];
#pragma unroll
                for (int p = 0; p < 2; p++) {
                    uint32_t off = SWZ((nRow + nh * 32 + p * 16) * 128 + kbase);
                    ldsm4(bh[p], sBhi + off);
                    ldsm4(bl[p], sBlo + off);
                }
#pragma unroll
                for (int mt = 0; mt < 2; mt++)
#pragma unroll
                    for (int p = 0; p < 2; p++)
#pragma unroll
                        for (int e = 0; e < 2; e++) {
                            float* d = acc[mt][nh * 4 + p * 2 + e];
                            mma16816(d, ah[mt], bh[p][e], bh[p][e + 2]);
                            mma16816(d, ah[mt], bl[p][e], bl[p][e + 2]);
                            mma16816(d, al[mt], bh[p][e], bh[p][e + 2]);
                        }
            }
        }
        // LDGs for chunk c+2 issue behind the MMA drain, consumed next iter
        if (c + 2 < NCH) buildX(c + 2);
        __syncthreads();         // all warps done reading stage st
    }

    // ---- epilogue: bias, relu, dot w2 ----
    // D frag rows: wm*32 + mt*16 + (lane>>2) and +8; cols wn*64 + nt*8 + (lane&3)*2
#pragma unroll
    for (int mt = 0; mt < 2; mt++) {
        float ps0 = 0.f, ps1 = 0.f;
#pragma unroll
        for (int nt = 0; nt < 8; nt++) {
            int h = wn * 64 + nt * 8 + (lane & 3) * 2;
            float b0 = s_b1[h],  w0 = s_w2[h];
            float b1v = s_b1[h + 1], w1v = s_w2[h + 1];
            ps0 = fmaf(fmaxf(acc[mt][nt][0] + b0, 0.f),  w0,  ps0);
            ps0 = fmaf(fmaxf(acc[mt][nt][1] + b1v, 0.f), w1v, ps0);
            ps1 = fmaf(fmaxf(acc[mt][nt][2] + b0, 0.f),  w0,  ps1);
            ps1 = fmaf(fmaxf(acc[mt][nt][3] + b1v, 0.f), w1v, ps1);
        }
        ps0 += __shfl_xor_sync(0xffffffffu, ps0, 1);
        ps0 += __shfl_xor_sync(0xffffffffu, ps0, 2);
        ps1 += __shfl_xor_sync(0xffffffffu, ps1, 1);
        ps1 += __shfl_xor_sync(0xffffffffu, ps1, 2);
        if ((lane & 3) == 0) {
            int r0 = wm * 32 + mt * 16 + (lane >> 2);
            red[r0][wn] = ps0;
            red[r0 + 8][wn] = ps1;
        }
    }
    __syncthreads();
    if (t < 128) rowlogit[t] = red[t][0] + red[t][1] + red[t][2] + red[t][3];
    __syncthreads();
    if (PHASE == 0) {
        if (t < 16) {
            float s = 0.f;
#pragma unroll
            for (int r = 0; r < 8; r++) s += rowlogit[t * 8 + r];
            outv[blockIdx.x * 16 + t] = s * 0.125f + b2[0];
        }
    } else {
        if (t < 128) outv[blockIdx.x * 128 + t] = rowlogit[t] + b2[0];
    }
}

// ---------------------------------------------------------------- top-64
__global__ __launch_bounds__(1024) void topk_kernel(const float* __restrict__ logits,
                                                    const float* __restrict__ mask,
                                                    float* __restrict__ out_inds) {
    const int t = threadIdx.x;
    const int wid = t >> 5, lane = t & 31;
    float v[16];
#pragma unroll
    for (int u = 0; u < 16; u++) {
        int p = u * 1024 + t;
        v[u] = (mask[p] != 0.f) ? logits[p] : -3.4e38f;
    }
    float lmax = -3.4e38f; int ls = 0;
#pragma unroll
    for (int u = 0; u < 16; u++) if (v[u] > lmax) { lmax = v[u]; ls = u; }

    __shared__ float wv[32];
    __shared__ int wi2[32];
    __shared__ int s_best;
    for (int sel = 0; sel < KTOP; sel++) {
        float bv = lmax;
        int bi = ls * 1024 + t;
#pragma unroll
        for (int o = 16; o > 0; o >>= 1) {
            float ov = __shfl_down_sync(0xffffffffu, bv, o);
            int oi = __shfl_down_sync(0xffffffffu, bi, o);
            if (ov > bv || (ov == bv && oi < bi)) { bv = ov; bi = oi; }
        }
        if (lane == 0) { wv[wid] = bv; wi2[wid] = bi; }
        __syncthreads();
        if (wid == 0) {
            bv = wv[lane]; bi = wi2[lane];
#pragma unroll
            for (int o = 16; o > 0; o >>= 1) {
                float ov = __shfl_down_sync(0xffffffffu, bv, o);
                int oi = __shfl_down_sync(0xffffffffu, bi, o);
                if (ov > bv || (ov == bv && oi < bi)) { bv = ov; bi = oi; }
            }
            if (lane == 0) { g_topk[sel] = bi; out_inds[sel] = (float)bi; s_best = bi; }
        }
        __syncthreads();
        int w = s_best;
        if ((w & 1023) == t) {
            v[w >> 10] = -3.4e38f;
            lmax = -3.4e38f; ls = 0;
#pragma unroll
            for (int u = 0; u < 16; u++) if (v[u] > lmax) { lmax = v[u]; ls = u; }
        }
    }
}

// ---------------------------------------------------------------- gather
__global__ void gather_pf_kernel(const float* __restrict__ obj,
                                 const float* __restrict__ geo) {
    const int b = blockIdx.x;
    const int ind = g_topk[b];
    const int i = ind >> 7, j = ind & 127;
    const int d = threadIdx.x * 4;
    float4 a = make_float4(0.f, 0.f, 0.f, 0.f);
#pragma unroll
    for (int r = 0; r < RR; r++) {
        const float4 oi = *(const float4*)&obj[(size_t)(r * NN + i) * DD + d];
        const float4 oj = *(const float4*)&obj[(size_t)(r * NN + j) * DD + d];
        const float4 g4 = *(const float4*)&geo[(size_t)((r * NN + i) * NN + j) * DD + d];
        a.x += fmaf(oi.x, oj.x, g4.x);
        a.y += fmaf(oi.y, oj.y, g4.y);
        a.z += fmaf(oi.z, oj.z, g4.z);
        a.w += fmaf(oi.w, oj.w, g4.w);
    }
    a.x *= (1.f / RR); a.y *= (1.f / RR); a.z *= (1.f / RR); a.w *= (1.f / RR);
    *(float4*)&g_pf[b * DD + d] = a;
}

// ---------------------------------------------------------------- launch
extern "C" void kernel_launch(void* const* d_in, const int* in_sizes, int n_in,
                              void* d_out, int out_size) {
    const float* obj  = (const float*)d_in[0];
    const float* geo  = (const float*)d_in[1];
    const float* mask = (const float*)d_in[2];
    const float* w1a  = (const float*)d_in[3];
    const float* b1a  = (const float*)d_in[4];
    const float* w2a  = (const float*)d_in[5];
    const float* b2a  = (const float*)d_in[6];
    const float* w1b  = (const float*)d_in[7];
    const float* b1b  = (const float*)d_in[8];
    const float* w2b  = (const float*)d_in[9];
    const float* b2b  = (const float*)d_in[10];
    float* out = (float*)d_out;

    const int dyn = 2 * STG + 1024;  // +1024 for manual alignment
    cudaFuncSetAttribute(gemm_mlp_kernel<0>,
                         cudaFuncAttributeMaxDynamicSharedMemorySize, dyn);
    cudaFuncSetAttribute(gemm_mlp_kernel<1>,
                         cudaFuncAttributeMaxDynamicSharedMemorySize, dyn);

    prep_w_kernel<<<1024, 256>>>(w1a, w1b);
    gemm_mlp_kernel<0><<<NPAIR / 16, 512, dyn>>>(obj, geo, b1a, w2a, b2a, out);
    topk_kernel<<<1, 1024>>>(out, mask, out + NPAIR + KTOP * KTOP);
    gather_pf_kernel<<<KTOP, 128>>>(obj, geo);
    gemm_mlp_kernel<1><<<KTOP * KTOP / 128, 512, dyn>>>(obj, geo, b1b, w2b, b2b,
                                                        out + NPAIR);
}